// round 3
// baseline (speedup 1.0000x reference)
#include <cuda_runtime.h>
#include <cuda_bf16.h>
#include <cstdint>

#define BB 2
#define TT 8192
#define DD 1024
#define MM (BB*TT)
#define PCH 128
#define TCH (TT/PCH)

// ----------------------------- device scratch ------------------------------
__device__ __align__(128) __nv_bfloat16 g_Xh[(size_t)MM*DD];
__device__ __align__(128) __nv_bfloat16 g_Xl[(size_t)MM*DD];
__device__ __align__(128) __nv_bfloat16 g_Wvh[DD*DD];
__device__ __align__(128) __nv_bfloat16 g_Wvl[DD*DD];
__device__ __align__(128) __nv_bfloat16 g_Woh[DD*DD];
__device__ __align__(128) __nv_bfloat16 g_Wol[DD*DD];
__device__ __align__(128) float         g_V[(size_t)MM*DD];
__device__ __align__(128) float2        g_part[BB*PCH*DD];
__device__ __align__(128) __nv_bfloat16 g_Rh[(size_t)MM*DD];
__device__ __align__(128) __nv_bfloat16 g_Rl[(size_t)MM*DD];

// ------------------------------ PTX helpers --------------------------------
__device__ __forceinline__ uint32_t smem_to_u32(const void* p) {
    uint32_t a;
    asm("{ .reg .u64 t; cvta.to.shared.u64 t, %1; cvt.u32.u64 %0, t; }" : "=r"(a) : "l"(p));
    return a;
}
#define SWZ(o) ((uint32_t)(o) ^ ((((uint32_t)(o)) >> 3) & 0x70))

#define CP_ASYNC16(dst, src) \
    asm volatile("cp.async.cg.shared.global [%0], [%1], 16;" :: "r"(dst), "l"(src))
#define CP_COMMIT() asm volatile("cp.async.commit_group;" ::: "memory")
#define CP_WAIT1() asm volatile("cp.async.wait_group 1;" ::: "memory")
#define CP_WAIT0() asm volatile("cp.async.wait_group 0;" ::: "memory")

#define LDMX4(r0, r1, r2, r3, addr) \
    asm volatile("ldmatrix.sync.aligned.m8n8.x4.shared.b16 {%0,%1,%2,%3}, [%4];" \
        : "=r"(r0), "=r"(r1), "=r"(r2), "=r"(r3) : "r"(addr))

#define MMA16816(d, a, b) \
    asm volatile("mma.sync.aligned.m16n8k16.row.col.f32.bf16.bf16.f32 " \
        "{%0,%1,%2,%3}, {%4,%5,%6,%7}, {%8,%9}, {%0,%1,%2,%3};" \
        : "+f"((d)[0]), "+f"((d)[1]), "+f"((d)[2]), "+f"((d)[3]) \
        : "r"((a)[0]), "r"((a)[1]), "r"((a)[2]), "r"((a)[3]), \
          "r"((b)[0]), "r"((b)[1]))

// ------------------------------- split -------------------------------------
__global__ void k_split(const float* __restrict__ in, int which) {
    size_t n; __nv_bfloat16 *hi, *lo;
    if (which == 0)      { n = (size_t)MM * DD; hi = g_Xh;  lo = g_Xl;  }
    else if (which == 1) { n = (size_t)DD * DD; hi = g_Wvh; lo = g_Wvl; }
    else                 { n = (size_t)DD * DD; hi = g_Woh; lo = g_Wol; }
    size_t n4 = n >> 2;
    const float4* in4 = (const float4*)in;
    __nv_bfloat162* h2 = (__nv_bfloat162*)hi;
    __nv_bfloat162* l2 = (__nv_bfloat162*)lo;
    for (size_t i = (size_t)blockIdx.x * blockDim.x + threadIdx.x; i < n4;
         i += (size_t)gridDim.x * blockDim.x) {
        float4 v = in4[i];
        __nv_bfloat16 h0 = __float2bfloat16(v.x), h1 = __float2bfloat16(v.y);
        __nv_bfloat16 h2e = __float2bfloat16(v.z), h3 = __float2bfloat16(v.w);
        __nv_bfloat162 a, b;
        a.x = h0; a.y = h1; b.x = h2e; b.y = h3;
        h2[2*i] = a; h2[2*i+1] = b;
        a.x = __float2bfloat16(v.x - __bfloat162float(h0));
        a.y = __float2bfloat16(v.y - __bfloat162float(h1));
        b.x = __float2bfloat16(v.z - __bfloat162float(h2e));
        b.y = __float2bfloat16(v.w - __bfloat162float(h3));
        l2[2*i] = a; l2[2*i+1] = b;
    }
}

// -------------------------------- GEMM -------------------------------------
// C[m,n] = sum_k A[m,k]*B[n,k];  A~Ah+Al, B~Bh+Bl;  C = Ah*Bh + Al*Bh + Ah*Bl
// CTA tile 128x128, BK=64 bf16 (128B SMEM rows, SW128 swizzle), cp.async
// double buffer, 8 warps in 4(m) x 2(n) grid, warp tile 32x64,
// mma.sync m16n8k16 bf16 (baseline PTX — tcgen05 unavailable on this target).
#define TILEB 16384          // 128 rows x 128B
#define B_BASE 32768
#define GSMEM 65536

__global__ void __launch_bounds__(256, 2)
k_gemm(int which, float* __restrict__ outC) {
    extern __shared__ __align__(1024) char smem[];
    const __nv_bfloat16 *Ah, *Al, *Bh, *Bl; float* C;
    if (which == 0) { Ah = g_Xh; Al = g_Xl; Bh = g_Wvh; Bl = g_Wvl; C = g_V; }
    else            { Ah = g_Rh; Al = g_Rl; Bh = g_Woh; Bl = g_Wol; C = outC; }

    const uint32_t sb = smem_to_u32(smem);
    const int tid = threadIdx.x, wid = tid >> 5, lid = tid & 31;
    const int warp_m = wid & 3, warp_n = wid >> 2;
    const int tn = blockIdx.x * 128, tm = blockIdx.y * 128;

    float acc[2][8][4];
    #pragma unroll
    for (int mi = 0; mi < 2; ++mi)
        #pragma unroll
        for (int ni = 0; ni < 8; ++ni)
            #pragma unroll
            for (int q = 0; q < 4; ++q) acc[mi][ni][q] = 0.f;

    // cp.async load of one K-chunk (64 bf16 wide) into buffer `buf`
    auto load_chunk = [&](int c, int buf) {
        const __nv_bfloat16 *As_, *Bs_;
        if (c < 16)      { As_ = Ah; Bs_ = Bh; }
        else if (c < 32) { As_ = Al; Bs_ = Bh; }
        else             { As_ = Ah; Bs_ = Bl; }
        const int k0 = (c & 15) << 6;
        const char* srcA = (const char*)(As_ + (size_t)tm * DD + k0);
        const char* srcB = (const char*)(Bs_ + (size_t)tn * DD + k0);
        const uint32_t dA = sb + buf * TILEB;
        const uint32_t dB = sb + B_BASE + buf * TILEB;
        #pragma unroll
        for (int i = 0; i < 4; ++i) {
            int j = tid + i * 256;
            int row = j >> 3, seg = j & 7;
            uint32_t off = SWZ((row << 7) | (seg << 4));
            size_t goff = (size_t)row * (DD * 2) + seg * 16;
            CP_ASYNC16(dA + off, srcA + goff);
            CP_ASYNC16(dB + off, srcB + goff);
        }
        CP_COMMIT();
    };

    load_chunk(0, 0);

    // per-lane ldmatrix row/col bases (x4 quad mapping)
    const int a_row = warp_m * 32 + (lid & 7) + ((lid >> 3) & 1) * 8;
    const int a_kof = ((lid >> 4) & 1) * 8;
    const int b_row = warp_n * 64 + (lid & 7) + ((lid >> 4) & 1) * 8;
    const int b_kof = ((lid >> 3) & 1) * 8;

    for (int c = 0; c < 48; ++c) {
        if (c + 1 < 48) { load_chunk(c + 1, (c + 1) & 1); CP_WAIT1(); }
        else            { CP_WAIT0(); }
        __syncthreads();

        const uint32_t aB = sb + (c & 1) * TILEB;
        const uint32_t bB = sb + B_BASE + (c & 1) * TILEB;
        #pragma unroll
        for (int kk = 0; kk < 4; ++kk) {
            uint32_t af[2][4], bf[8][2];
            #pragma unroll
            for (int mi = 0; mi < 2; ++mi) {
                uint32_t addr = aB + SWZ(((a_row + mi * 16) << 7) | ((a_kof + kk * 16) << 1));
                LDMX4(af[mi][0], af[mi][1], af[mi][2], af[mi][3], addr);
            }
            #pragma unroll
            for (int ni = 0; ni < 4; ++ni) {
                uint32_t r0, r1, r2, r3;
                uint32_t addr = bB + SWZ(((b_row + ni * 16) << 7) | ((b_kof + kk * 16) << 1));
                LDMX4(r0, r1, r2, r3, addr);
                bf[2*ni][0] = r0; bf[2*ni][1] = r1;
                bf[2*ni+1][0] = r2; bf[2*ni+1][1] = r3;
            }
            #pragma unroll
            for (int mi = 0; mi < 2; ++mi)
                #pragma unroll
                for (int ni = 0; ni < 8; ++ni)
                    MMA16816(acc[mi][ni], af[mi], bf[ni]);
        }
        __syncthreads();
    }

    // epilogue: direct float2 stores
    #pragma unroll
    for (int mi = 0; mi < 2; ++mi) {
        int m = tm + warp_m * 32 + mi * 16 + (lid >> 2);
        int n0 = tn + warp_n * 64 + (lid & 3) * 2;
        float* r0p = C + (size_t)m * DD + n0;
        float* r1p = C + (size_t)(m + 8) * DD + n0;
        #pragma unroll
        for (int ni = 0; ni < 8; ++ni) {
            *(float2*)(r0p + ni * 8) = make_float2(acc[mi][ni][0], acc[mi][ni][1]);
            *(float2*)(r1p + ni * 8) = make_float2(acc[mi][ni][2], acc[mi][ni][3]);
        }
    }
}

// ------------------------------- scan --------------------------------------
__device__ __forceinline__ void rot_sincos(float ph, float* s, float* c) {
    // exact fp64 range reduction of the fp32 phase; sinf/cosf accurate on |r|<=pi
    double th = (double)ph;
    double q = rint(th * 0.15915494309189535);
    float r = (float)(th - q * 6.283185307179586);
    *s = sinf(r); *c = cosf(r);
}

__global__ void k_pass1(const float* __restrict__ freqs) {
    const int b = blockIdx.y, ch = blockIdx.x, tid = threadIdx.x;
    float f[4]; float2 acc[4];
    #pragma unroll
    for (int j = 0; j < 4; ++j) { f[j] = freqs[tid + j*256]; acc[j] = make_float2(0.f, 0.f); }
    const float* vp = g_V + ((size_t)b * TT + (size_t)ch * TCH) * DD + tid;
    for (int tl = 0; tl < TCH; ++tl) {
        float t = (float)(ch * TCH + tl);
        #pragma unroll
        for (int j = 0; j < 4; ++j) {
            float s, c; rot_sincos(t * f[j], &s, &c);
            float v = vp[j*256];
            acc[j].x += v * c; acc[j].y += v * s;
        }
        vp += DD;
    }
    #pragma unroll
    for (int j = 0; j < 4; ++j)
        g_part[((size_t)b * PCH + ch) * DD + tid + j*256] = acc[j];
}

__global__ void k_pass2() {
    int id = blockIdx.x * blockDim.x + threadIdx.x;   // 0..2047
    int b = id >> 10, d = id & 1023;
    float2 run = make_float2(0.f, 0.f);
    for (int ch = 0; ch < PCH; ++ch) {
        size_t i = ((size_t)b * PCH + ch) * DD + d;
        float2 v = g_part[i];
        g_part[i] = run;
        run.x += v.x; run.y += v.y;
    }
}

__global__ void k_pass3(const float* __restrict__ freqs) {
    const int b = blockIdx.y, ch = blockIdx.x, tid = threadIdx.x;
    float f[4]; float2 acc[4];
    #pragma unroll
    for (int j = 0; j < 4; ++j) {
        f[j] = freqs[tid + j*256];
        acc[j] = g_part[((size_t)b * PCH + ch) * DD + tid + j*256];
    }
    size_t base = ((size_t)b * TT + (size_t)ch * TCH) * DD + tid;
    const float* vp = g_V + base;
    __nv_bfloat16* rh = g_Rh + base;
    __nv_bfloat16* rl = g_Rl + base;
    for (int tl = 0; tl < TCH; ++tl) {
        float t = (float)(ch * TCH + tl);
        #pragma unroll
        for (int j = 0; j < 4; ++j) {
            float s, c; rot_sincos(t * f[j], &s, &c);
            float v = vp[j*256];
            acc[j].x += v * c; acc[j].y += v * s;
            float ret = acc[j].x * c + acc[j].y * s;
            __nv_bfloat16 h = __float2bfloat16(ret);
            rh[j*256] = h;
            rl[j*256] = __float2bfloat16(ret - __bfloat162float(h));
        }
        vp += DD; rh += DD; rl += DD;
    }
}

// ------------------------------- launch ------------------------------------
extern "C" void kernel_launch(void* const* d_in, const int* in_sizes, int n_in,
                              void* d_out, int out_size) {
    const float* x     = (const float*)d_in[0];
    const float* Wv    = (const float*)d_in[2];
    const float* Wo    = (const float*)d_in[3];
    const float* freqs = (const float*)d_in[4];
    float* out = (float*)d_out;

    static int smem_set = 0;
    if (!smem_set) {
        cudaFuncSetAttribute(k_gemm, cudaFuncAttributeMaxDynamicSharedMemorySize, GSMEM);
        smem_set = 1;
    }

    k_split<<<2048, 256>>>(x, 0);
    k_split<<<256, 256>>>(Wv, 1);
    k_split<<<256, 256>>>(Wo, 2);

    k_gemm<<<dim3(8, 128), 256, GSMEM>>>(0, nullptr);

    k_pass1<<<dim3(PCH, BB), 256>>>(freqs);
    k_pass2<<<8, 256>>>();
    k_pass3<<<dim3(PCH, BB), 256>>>(freqs);

    k_gemm<<<dim3(8, 128), 256, GSMEM>>>(1, out);
}

// round 4
// speedup vs baseline: 1.3603x; 1.3603x over previous
#include <cuda_runtime.h>
#include <cuda_bf16.h>
#include <cstdint>

#define BB 2
#define TT 8192
#define DD 1024
#define MM (BB*TT)
#define PCH 128
#define TCH (TT/PCH)

// ----------------------------- device scratch ------------------------------
__device__ __align__(128) __nv_bfloat16 g_Xh[(size_t)MM*DD];
__device__ __align__(128) __nv_bfloat16 g_Xl[(size_t)MM*DD];
__device__ __align__(128) __nv_bfloat16 g_Wvh[DD*DD];
__device__ __align__(128) __nv_bfloat16 g_Wvl[DD*DD];
__device__ __align__(128) __nv_bfloat16 g_Woh[DD*DD];
__device__ __align__(128) __nv_bfloat16 g_Wol[DD*DD];
__device__ __align__(128) float         g_V[(size_t)MM*DD];
__device__ __align__(128) float2        g_part[BB*PCH*DD];
__device__ __align__(128) __nv_bfloat16 g_Rh[(size_t)MM*DD];
__device__ __align__(128) __nv_bfloat16 g_Rl[(size_t)MM*DD];

// ------------------------------ PTX helpers --------------------------------
__device__ __forceinline__ uint32_t smem_to_u32(const void* p) {
    uint32_t a;
    asm("{ .reg .u64 t; cvta.to.shared.u64 t, %1; cvt.u32.u64 %0, t; }" : "=r"(a) : "l"(p));
    return a;
}
#define SWZ(o) ((uint32_t)(o) ^ ((((uint32_t)(o)) >> 3) & 0x70))

#define CP_ASYNC16(dst, src) \
    asm volatile("cp.async.cg.shared.global [%0], [%1], 16;" :: "r"(dst), "l"(src))
#define CP_COMMIT() asm volatile("cp.async.commit_group;" ::: "memory")
#define CP_WAIT1() asm volatile("cp.async.wait_group 1;" ::: "memory")
#define CP_WAIT0() asm volatile("cp.async.wait_group 0;" ::: "memory")

#define LDMX4(r0, r1, r2, r3, addr) \
    asm volatile("ldmatrix.sync.aligned.m8n8.x4.shared.b16 {%0,%1,%2,%3}, [%4];" \
        : "=r"(r0), "=r"(r1), "=r"(r2), "=r"(r3) : "r"(addr))

#define MMA16816(d, a, b) \
    asm volatile("mma.sync.aligned.m16n8k16.row.col.f32.bf16.bf16.f32 " \
        "{%0,%1,%2,%3}, {%4,%5,%6,%7}, {%8,%9}, {%0,%1,%2,%3};" \
        : "+f"((d)[0]), "+f"((d)[1]), "+f"((d)[2]), "+f"((d)[3]) \
        : "r"((a)[0]), "r"((a)[1]), "r"((a)[2]), "r"((a)[3]), \
          "r"((b)[0]), "r"((b)[1]))

// ------------------------------- split -------------------------------------
__global__ void k_split(const float* __restrict__ in, int which) {
    size_t n; __nv_bfloat16 *hi, *lo;
    if (which == 0)      { n = (size_t)MM * DD; hi = g_Xh;  lo = g_Xl;  }
    else if (which == 1) { n = (size_t)DD * DD; hi = g_Wvh; lo = g_Wvl; }
    else                 { n = (size_t)DD * DD; hi = g_Woh; lo = g_Wol; }
    size_t n4 = n >> 2;
    const float4* in4 = (const float4*)in;
    __nv_bfloat162* h2 = (__nv_bfloat162*)hi;
    __nv_bfloat162* l2 = (__nv_bfloat162*)lo;
    for (size_t i = (size_t)blockIdx.x * blockDim.x + threadIdx.x; i < n4;
         i += (size_t)gridDim.x * blockDim.x) {
        float4 v = in4[i];
        __nv_bfloat16 h0 = __float2bfloat16(v.x), h1 = __float2bfloat16(v.y);
        __nv_bfloat16 h2e = __float2bfloat16(v.z), h3 = __float2bfloat16(v.w);
        __nv_bfloat162 a, b;
        a.x = h0; a.y = h1; b.x = h2e; b.y = h3;
        h2[2*i] = a; h2[2*i+1] = b;
        a.x = __float2bfloat16(v.x - __bfloat162float(h0));
        a.y = __float2bfloat16(v.y - __bfloat162float(h1));
        b.x = __float2bfloat16(v.z - __bfloat162float(h2e));
        b.y = __float2bfloat16(v.w - __bfloat162float(h3));
        l2[2*i] = a; l2[2*i+1] = b;
    }
}

// -------------------------------- GEMM -------------------------------------
// C[m,n] = sum_k A[m,k]*B[n,k];  A~Ah+Al, B~Bh+Bl;  C = Ah*Bh + Al*Bh + Ah*Bl
// (unchanged from R3: tensor=75.2%, 225.7us per launch)
#define TILEB 16384          // 128 rows x 128B
#define B_BASE 32768
#define GSMEM 65536

__global__ void __launch_bounds__(256, 2)
k_gemm(int which, float* __restrict__ outC) {
    extern __shared__ __align__(1024) char smem[];
    const __nv_bfloat16 *Ah, *Al, *Bh, *Bl; float* C;
    if (which == 0) { Ah = g_Xh; Al = g_Xl; Bh = g_Wvh; Bl = g_Wvl; C = g_V; }
    else            { Ah = g_Rh; Al = g_Rl; Bh = g_Woh; Bl = g_Wol; C = outC; }

    const uint32_t sb = smem_to_u32(smem);
    const int tid = threadIdx.x, wid = tid >> 5, lid = tid & 31;
    const int warp_m = wid & 3, warp_n = wid >> 2;
    const int tn = blockIdx.x * 128, tm = blockIdx.y * 128;

    float acc[2][8][4];
    #pragma unroll
    for (int mi = 0; mi < 2; ++mi)
        #pragma unroll
        for (int ni = 0; ni < 8; ++ni)
            #pragma unroll
            for (int q = 0; q < 4; ++q) acc[mi][ni][q] = 0.f;

    auto load_chunk = [&](int c, int buf) {
        const __nv_bfloat16 *As_, *Bs_;
        if (c < 16)      { As_ = Ah; Bs_ = Bh; }
        else if (c < 32) { As_ = Al; Bs_ = Bh; }
        else             { As_ = Ah; Bs_ = Bl; }
        const int k0 = (c & 15) << 6;
        const char* srcA = (const char*)(As_ + (size_t)tm * DD + k0);
        const char* srcB = (const char*)(Bs_ + (size_t)tn * DD + k0);
        const uint32_t dA = sb + buf * TILEB;
        const uint32_t dB = sb + B_BASE + buf * TILEB;
        #pragma unroll
        for (int i = 0; i < 4; ++i) {
            int j = tid + i * 256;
            int row = j >> 3, seg = j & 7;
            uint32_t off = SWZ((row << 7) | (seg << 4));
            size_t goff = (size_t)row * (DD * 2) + seg * 16;
            CP_ASYNC16(dA + off, srcA + goff);
            CP_ASYNC16(dB + off, srcB + goff);
        }
        CP_COMMIT();
    };

    load_chunk(0, 0);

    const int a_row = warp_m * 32 + (lid & 7) + ((lid >> 3) & 1) * 8;
    const int a_kof = ((lid >> 4) & 1) * 8;
    const int b_row = warp_n * 64 + (lid & 7) + ((lid >> 4) & 1) * 8;
    const int b_kof = ((lid >> 3) & 1) * 8;

    for (int c = 0; c < 48; ++c) {
        if (c + 1 < 48) { load_chunk(c + 1, (c + 1) & 1); CP_WAIT1(); }
        else            { CP_WAIT0(); }
        __syncthreads();

        const uint32_t aB = sb + (c & 1) * TILEB;
        const uint32_t bB = sb + B_BASE + (c & 1) * TILEB;
        #pragma unroll
        for (int kk = 0; kk < 4; ++kk) {
            uint32_t af[2][4], bf[8][2];
            #pragma unroll
            for (int mi = 0; mi < 2; ++mi) {
                uint32_t addr = aB + SWZ(((a_row + mi * 16) << 7) | ((a_kof + kk * 16) << 1));
                LDMX4(af[mi][0], af[mi][1], af[mi][2], af[mi][3], addr);
            }
            #pragma unroll
            for (int ni = 0; ni < 4; ++ni) {
                uint32_t r0, r1, r2, r3;
                uint32_t addr = bB + SWZ(((b_row + ni * 16) << 7) | ((b_kof + kk * 16) << 1));
                LDMX4(r0, r1, r2, r3, addr);
                bf[2*ni][0] = r0; bf[2*ni][1] = r1;
                bf[2*ni+1][0] = r2; bf[2*ni+1][1] = r3;
            }
            #pragma unroll
            for (int mi = 0; mi < 2; ++mi)
                #pragma unroll
                for (int ni = 0; ni < 8; ++ni)
                    MMA16816(acc[mi][ni], af[mi], bf[ni]);
        }
        __syncthreads();
    }

    #pragma unroll
    for (int mi = 0; mi < 2; ++mi) {
        int m = tm + warp_m * 32 + mi * 16 + (lid >> 2);
        int n0 = tn + warp_n * 64 + (lid & 3) * 2;
        float* r0p = C + (size_t)m * DD + n0;
        float* r1p = C + (size_t)(m + 8) * DD + n0;
        #pragma unroll
        for (int ni = 0; ni < 8; ++ni) {
            *(float2*)(r0p + ni * 8) = make_float2(acc[mi][ni][0], acc[mi][ni][1]);
            *(float2*)(r1p + ni * 8) = make_float2(acc[mi][ni][2], acc[mi][ni][3]);
        }
    }
}

// ------------------------------- scan --------------------------------------
// Exact reproduction of reference phase: ph = fl32(t*f). Reduce ph mod 2*pi
// with a 3-term fp32 Cody-Waite (all constants compile-time; q <= 8192 is a
// 13-bit integer, H has a 6-bit mantissa, so q*H is exact). Total phase error
// < 1e-6 rad. Then MUFU sin/cos on |r| <= pi (abs err ~2^-21). No runtime fp64.
__device__ __forceinline__ void rot_sincos(float ph, float* s, float* c) {
    constexpr double TP = 6.283185307179586;
    constexpr float H = 6.28125f;
    constexpr float Mv = (float)(TP - (double)H);
    constexpr float L  = (float)(TP - (double)H - (double)Mv);
    float q = rintf(ph * 0.15915494309189535f);
    float r = fmaf(q, -H, ph);
    r = fmaf(q, -Mv, r);
    r = fmaf(q, -L, r);
    *s = __sinf(r); *c = __cosf(r);
}

__global__ void k_pass1(const float* __restrict__ freqs) {
    const int b = blockIdx.y, ch = blockIdx.x, tid = threadIdx.x;
    float f[4]; float2 acc[4];
    #pragma unroll
    for (int j = 0; j < 4; ++j) { f[j] = freqs[tid + j*256]; acc[j] = make_float2(0.f, 0.f); }
    const float* vp = g_V + ((size_t)b * TT + (size_t)ch * TCH) * DD + tid;
    for (int tl = 0; tl < TCH; ++tl) {
        float t = (float)(ch * TCH + tl);
        #pragma unroll
        for (int j = 0; j < 4; ++j) {
            float s, c; rot_sincos(t * f[j], &s, &c);
            float v = vp[j*256];
            acc[j].x += v * c; acc[j].y += v * s;
        }
        vp += DD;
    }
    #pragma unroll
    for (int j = 0; j < 4; ++j)
        g_part[((size_t)b * PCH + ch) * DD + tid + j*256] = acc[j];
}

__global__ void k_pass2() {
    int id = blockIdx.x * blockDim.x + threadIdx.x;   // 0..2047
    int b = id >> 10, d = id & 1023;
    float2 run = make_float2(0.f, 0.f);
    size_t base = (size_t)b * PCH * DD + d;
    for (int ch = 0; ch < PCH; ch += 4) {
        // batch 4 independent loads ahead of the dependent running sum (MLP=4)
        float2 v0 = g_part[base + (size_t)(ch+0)*DD];
        float2 v1 = g_part[base + (size_t)(ch+1)*DD];
        float2 v2 = g_part[base + (size_t)(ch+2)*DD];
        float2 v3 = g_part[base + (size_t)(ch+3)*DD];
        g_part[base + (size_t)(ch+0)*DD] = run; run.x += v0.x; run.y += v0.y;
        g_part[base + (size_t)(ch+1)*DD] = run; run.x += v1.x; run.y += v1.y;
        g_part[base + (size_t)(ch+2)*DD] = run; run.x += v2.x; run.y += v2.y;
        g_part[base + (size_t)(ch+3)*DD] = run; run.x += v3.x; run.y += v3.y;
    }
}

__global__ void k_pass3(const float* __restrict__ freqs) {
    const int b = blockIdx.y, ch = blockIdx.x, tid = threadIdx.x;
    float f[4]; float2 acc[4];
    #pragma unroll
    for (int j = 0; j < 4; ++j) {
        f[j] = freqs[tid + j*256];
        acc[j] = g_part[((size_t)b * PCH + ch) * DD + tid + j*256];
    }
    size_t base = ((size_t)b * TT + (size_t)ch * TCH) * DD + tid;
    const float* vp = g_V + base;
    __nv_bfloat16* rh = g_Rh + base;
    __nv_bfloat16* rl = g_Rl + base;
    for (int tl = 0; tl < TCH; ++tl) {
        float t = (float)(ch * TCH + tl);
        #pragma unroll
        for (int j = 0; j < 4; ++j) {
            float s, c; rot_sincos(t * f[j], &s, &c);
            float v = vp[j*256];
            acc[j].x += v * c; acc[j].y += v * s;
            float ret = acc[j].x * c + acc[j].y * s;
            __nv_bfloat16 h = __float2bfloat16(ret);
            rh[j*256] = h;
            rl[j*256] = __float2bfloat16(ret - __bfloat162float(h));
        }
        vp += DD; rh += DD; rl += DD;
    }
}

// ------------------------------- launch ------------------------------------
extern "C" void kernel_launch(void* const* d_in, const int* in_sizes, int n_in,
                              void* d_out, int out_size) {
    const float* x     = (const float*)d_in[0];
    const float* Wv    = (const float*)d_in[2];
    const float* Wo    = (const float*)d_in[3];
    const float* freqs = (const float*)d_in[4];
    float* out = (float*)d_out;

    static int smem_set = 0;
    if (!smem_set) {
        cudaFuncSetAttribute(k_gemm, cudaFuncAttributeMaxDynamicSharedMemorySize, GSMEM);
        smem_set = 1;
    }

    k_split<<<2048, 256>>>(x, 0);
    k_split<<<256, 256>>>(Wv, 1);
    k_split<<<256, 256>>>(Wo, 2);

    k_gemm<<<dim3(8, 128), 256, GSMEM>>>(0, nullptr);

    k_pass1<<<dim3(PCH, BB), 256>>>(freqs);
    k_pass2<<<64, 32>>>();
    k_pass3<<<dim3(PCH, BB), 256>>>(freqs);

    k_gemm<<<dim3(8, 128), 256, GSMEM>>>(1, out);
}

// round 5
// speedup vs baseline: 1.5540x; 1.1424x over previous
#include <cuda_runtime.h>
#include <cuda_fp16.h>
#include <cstdint>

#define BB 2
#define TT 8192
#define DD 1024
#define MM (BB*TT)
#define PCH 128
#define TCH (TT/PCH)

// ----------------------------- device scratch ------------------------------
__device__ __align__(128) __half g_Xh[(size_t)MM*DD];
__device__ __align__(128) __half g_Xl[(size_t)MM*DD];
__device__ __align__(128) __half g_Wvh[DD*DD];
__device__ __align__(128) __half g_Wvl[DD*DD];
__device__ __align__(128) __half g_Woh[DD*DD];
__device__ __align__(128) __half g_Wol[DD*DD];
__device__ __align__(128) float  g_V[(size_t)MM*DD];
__device__ __align__(128) float2 g_part[BB*PCH*DD];
__device__ __align__(128) __half g_Rh[(size_t)MM*DD];
__device__ __align__(128) __half g_Rl[(size_t)MM*DD];
__device__ __align__(128) float2 g_rot[(size_t)TT*DD];   // cached (cos,sin) per (t,d)

// ------------------------------ PTX helpers --------------------------------
__device__ __forceinline__ uint32_t smem_to_u32(const void* p) {
    uint32_t a;
    asm("{ .reg .u64 t; cvta.to.shared.u64 t, %1; cvt.u32.u64 %0, t; }" : "=r"(a) : "l"(p));
    return a;
}
#define SWZ(o) ((uint32_t)(o) ^ ((((uint32_t)(o)) >> 3) & 0x70))

#define CP_ASYNC16(dst, src) \
    asm volatile("cp.async.cg.shared.global [%0], [%1], 16;" :: "r"(dst), "l"(src))
#define CP_COMMIT() asm volatile("cp.async.commit_group;" ::: "memory")
#define CP_WAIT1() asm volatile("cp.async.wait_group 1;" ::: "memory")
#define CP_WAIT0() asm volatile("cp.async.wait_group 0;" ::: "memory")

#define LDMX4(r0, r1, r2, r3, addr) \
    asm volatile("ldmatrix.sync.aligned.m8n8.x4.shared.b16 {%0,%1,%2,%3}, [%4];" \
        : "=r"(r0), "=r"(r1), "=r"(r2), "=r"(r3) : "r"(addr))

#define MMA16816(d, a, b) \
    asm volatile("mma.sync.aligned.m16n8k16.row.col.f32.f16.f16.f32 " \
        "{%0,%1,%2,%3}, {%4,%5,%6,%7}, {%8,%9}, {%0,%1,%2,%3};" \
        : "+f"((d)[0]), "+f"((d)[1]), "+f"((d)[2]), "+f"((d)[3]) \
        : "r"((a)[0]), "r"((a)[1]), "r"((a)[2]), "r"((a)[3]), \
          "r"((b)[0]), "r"((b)[1]))

// ------------------------------- split -------------------------------------
// fp32 -> fp16 hi + fp16 lo (2-term; residual ~2^-22 relative)
__global__ void k_split(const float* __restrict__ in, int which) {
    size_t n; __half *hi, *lo;
    if (which == 0)      { n = (size_t)MM * DD; hi = g_Xh;  lo = g_Xl;  }
    else if (which == 1) { n = (size_t)DD * DD; hi = g_Wvh; lo = g_Wvl; }
    else                 { n = (size_t)DD * DD; hi = g_Woh; lo = g_Wol; }
    size_t n4 = n >> 2;
    const float4* in4 = (const float4*)in;
    __half2* h2 = (__half2*)hi;
    __half2* l2 = (__half2*)lo;
    for (size_t i = (size_t)blockIdx.x * blockDim.x + threadIdx.x; i < n4;
         i += (size_t)gridDim.x * blockDim.x) {
        float4 v = in4[i];
        __half h0 = __float2half(v.x), h1 = __float2half(v.y);
        __half h2e = __float2half(v.z), h3 = __float2half(v.w);
        __half2 a, b;
        a.x = h0; a.y = h1; b.x = h2e; b.y = h3;
        h2[2*i] = a; h2[2*i+1] = b;
        a.x = __float2half(v.x - __half2float(h0));
        a.y = __float2half(v.y - __half2float(h1));
        b.x = __float2half(v.z - __half2float(h2e));
        b.y = __float2half(v.w - __half2float(h3));
        l2[2*i] = a; l2[2*i+1] = b;
    }
}

// -------------------------------- GEMM -------------------------------------
// C[m,n] = sum_k A[m,k]*B[n,k];  A~Ah+Al (fp16);  C = Ah*Bh + Al*Bh
// (drop Ah*Bl: incoherent ~1.4e-4 relative, well inside 1e-3)
#define TILEB 16384          // 128 rows x 128B
#define B_BASE 32768
#define GSMEM 65536
#define NCHUNK 32

__global__ void __launch_bounds__(256, 2)
k_gemm(int which, float* __restrict__ outC) {
    extern __shared__ __align__(1024) char smem[];
    const __half *Ah, *Al, *Bh; float* C;
    if (which == 0) { Ah = g_Xh; Al = g_Xl; Bh = g_Wvh; C = g_V; }
    else            { Ah = g_Rh; Al = g_Rl; Bh = g_Woh; C = outC; }

    const uint32_t sb = smem_to_u32(smem);
    const int tid = threadIdx.x, wid = tid >> 5, lid = tid & 31;
    const int warp_m = wid & 3, warp_n = wid >> 2;
    const int tn = blockIdx.x * 128, tm = blockIdx.y * 128;

    float acc[2][8][4];
    #pragma unroll
    for (int mi = 0; mi < 2; ++mi)
        #pragma unroll
        for (int ni = 0; ni < 8; ++ni)
            #pragma unroll
            for (int q = 0; q < 4; ++q) acc[mi][ni][q] = 0.f;

    auto load_chunk = [&](int c, int buf) {
        const __half* As_ = (c < 16) ? Ah : Al;
        const int k0 = (c & 15) << 6;
        const char* srcA = (const char*)(As_ + (size_t)tm * DD + k0);
        const char* srcB = (const char*)(Bh + (size_t)tn * DD + k0);
        const uint32_t dA = sb + buf * TILEB;
        const uint32_t dB = sb + B_BASE + buf * TILEB;
        #pragma unroll
        for (int i = 0; i < 4; ++i) {
            int j = tid + i * 256;
            int row = j >> 3, seg = j & 7;
            uint32_t off = SWZ((row << 7) | (seg << 4));
            size_t goff = (size_t)row * (DD * 2) + seg * 16;
            CP_ASYNC16(dA + off, srcA + goff);
            CP_ASYNC16(dB + off, srcB + goff);
        }
        CP_COMMIT();
    };

    load_chunk(0, 0);

    const int a_row = warp_m * 32 + (lid & 7) + ((lid >> 3) & 1) * 8;
    const int a_kof = ((lid >> 4) & 1) * 8;
    const int b_row = warp_n * 64 + (lid & 7) + ((lid >> 4) & 1) * 8;
    const int b_kof = ((lid >> 3) & 1) * 8;

    for (int c = 0; c < NCHUNK; ++c) {
        if (c + 1 < NCHUNK) { load_chunk(c + 1, (c + 1) & 1); CP_WAIT1(); }
        else                { CP_WAIT0(); }
        __syncthreads();

        const uint32_t aB = sb + (c & 1) * TILEB;
        const uint32_t bB = sb + B_BASE + (c & 1) * TILEB;
        #pragma unroll
        for (int kk = 0; kk < 4; ++kk) {
            uint32_t af[2][4], bf[8][2];
            #pragma unroll
            for (int mi = 0; mi < 2; ++mi) {
                uint32_t addr = aB + SWZ(((a_row + mi * 16) << 7) | ((a_kof + kk * 16) << 1));
                LDMX4(af[mi][0], af[mi][1], af[mi][2], af[mi][3], addr);
            }
            #pragma unroll
            for (int ni = 0; ni < 4; ++ni) {
                uint32_t r0, r1, r2, r3;
                uint32_t addr = bB + SWZ(((b_row + ni * 16) << 7) | ((b_kof + kk * 16) << 1));
                LDMX4(r0, r1, r2, r3, addr);
                bf[2*ni][0] = r0; bf[2*ni][1] = r1;
                bf[2*ni+1][0] = r2; bf[2*ni+1][1] = r3;
            }
            #pragma unroll
            for (int mi = 0; mi < 2; ++mi)
                #pragma unroll
                for (int ni = 0; ni < 8; ++ni)
                    MMA16816(acc[mi][ni], af[mi], bf[ni]);
        }
        __syncthreads();
    }

    #pragma unroll
    for (int mi = 0; mi < 2; ++mi) {
        int m = tm + warp_m * 32 + mi * 16 + (lid >> 2);
        int n0 = tn + warp_n * 64 + (lid & 3) * 2;
        float* r0p = C + (size_t)m * DD + n0;
        float* r1p = C + (size_t)(m + 8) * DD + n0;
        #pragma unroll
        for (int ni = 0; ni < 8; ++ni) {
            *(float2*)(r0p + ni * 8) = make_float2(acc[mi][ni][0], acc[mi][ni][1]);
            *(float2*)(r1p + ni * 8) = make_float2(acc[mi][ni][2], acc[mi][ni][3]);
        }
    }
}

// ------------------------------- scan --------------------------------------
// ph = fl32(t*f) (exact reproduction of reference rounding), then 3-term fp32
// Cody-Waite reduction (constants compile-time; q<=8192 13-bit, H 6-bit
// mantissa -> q*H exact). MUFU sin/cos on |r|<=pi.
__device__ __forceinline__ void rot_sincos(float ph, float* s, float* c) {
    constexpr double TP = 6.283185307179586;
    constexpr float H = 6.28125f;
    constexpr float Mv = (float)(TP - (double)H);
    constexpr float L  = (float)(TP - (double)H - (double)Mv);
    float q = rintf(ph * 0.15915494309189535f);
    float r = fmaf(q, -H, ph);
    r = fmaf(q, -Mv, r);
    r = fmaf(q, -L, r);
    *s = __sinf(r); *c = __cosf(r);
}

__global__ void k_pass1(const float* __restrict__ freqs) {
    const int b = blockIdx.y, ch = blockIdx.x, tid = threadIdx.x;
    float f[4]; float2 acc[4];
    #pragma unroll
    for (int j = 0; j < 4; ++j) { f[j] = freqs[tid + j*256]; acc[j] = make_float2(0.f, 0.f); }
    const float* vp = g_V + ((size_t)b * TT + (size_t)ch * TCH) * DD + tid;
    float2* rp = g_rot + (size_t)ch * TCH * DD + tid;
    for (int tl = 0; tl < TCH; ++tl) {
        float t = (float)(ch * TCH + tl);
        #pragma unroll
        for (int j = 0; j < 4; ++j) {
            float s, c; rot_sincos(t * f[j], &s, &c);
            float v = vp[j*256];
            acc[j].x += v * c; acc[j].y += v * s;
            if (b == 0) rp[j*256] = make_float2(c, s);   // cache rotor for pass3
        }
        vp += DD; rp += DD;
    }
    #pragma unroll
    for (int j = 0; j < 4; ++j)
        g_part[((size_t)b * PCH + ch) * DD + tid + j*256] = acc[j];
}

__global__ void k_pass2() {
    int id = blockIdx.x * blockDim.x + threadIdx.x;   // 0..2047
    int b = id >> 10, d = id & 1023;
    float2 run = make_float2(0.f, 0.f);
    size_t base = (size_t)b * PCH * DD + d;
    for (int ch = 0; ch < PCH; ch += 4) {
        float2 v0 = g_part[base + (size_t)(ch+0)*DD];
        float2 v1 = g_part[base + (size_t)(ch+1)*DD];
        float2 v2 = g_part[base + (size_t)(ch+2)*DD];
        float2 v3 = g_part[base + (size_t)(ch+3)*DD];
        g_part[base + (size_t)(ch+0)*DD] = run; run.x += v0.x; run.y += v0.y;
        g_part[base + (size_t)(ch+1)*DD] = run; run.x += v1.x; run.y += v1.y;
        g_part[base + (size_t)(ch+2)*DD] = run; run.x += v2.x; run.y += v2.y;
        g_part[base + (size_t)(ch+3)*DD] = run; run.x += v3.x; run.y += v3.y;
    }
}

__global__ void k_pass3(const float* __restrict__ freqs) {
    const int b = blockIdx.y, ch = blockIdx.x, tid = threadIdx.x;
    float2 acc[4];
    #pragma unroll
    for (int j = 0; j < 4; ++j)
        acc[j] = g_part[((size_t)b * PCH + ch) * DD + tid + j*256];
    size_t base = ((size_t)b * TT + (size_t)ch * TCH) * DD + tid;
    const float* vp = g_V + base;
    const float2* rp = g_rot + (size_t)ch * TCH * DD + tid;
    __half* rh = g_Rh + base;
    __half* rl = g_Rl + base;
    for (int tl = 0; tl < TCH; ++tl) {
        #pragma unroll
        for (int j = 0; j < 4; ++j) {
            float2 cs = rp[j*256];
            float v = vp[j*256];
            acc[j].x += v * cs.x; acc[j].y += v * cs.y;
            float ret = acc[j].x * cs.x + acc[j].y * cs.y;
            __half h = __float2half(ret);
            rh[j*256] = h;
            rl[j*256] = __float2half(ret - __half2float(h));
        }
        vp += DD; rp += DD; rh += DD; rl += DD;
    }
}

// ------------------------------- launch ------------------------------------
extern "C" void kernel_launch(void* const* d_in, const int* in_sizes, int n_in,
                              void* d_out, int out_size) {
    const float* x     = (const float*)d_in[0];
    const float* Wv    = (const float*)d_in[2];
    const float* Wo    = (const float*)d_in[3];
    const float* freqs = (const float*)d_in[4];
    float* out = (float*)d_out;

    static int smem_set = 0;
    if (!smem_set) {
        cudaFuncSetAttribute(k_gemm, cudaFuncAttributeMaxDynamicSharedMemorySize, GSMEM);
        smem_set = 1;
    }

    k_split<<<2048, 256>>>(x, 0);
    k_split<<<256, 256>>>(Wv, 1);
    k_split<<<256, 256>>>(Wo, 2);

    k_gemm<<<dim3(8, 128), 256, GSMEM>>>(0, nullptr);

    k_pass1<<<dim3(PCH, BB), 256>>>(freqs);
    k_pass2<<<64, 32>>>();
    k_pass3<<<dim3(PCH, BB), 256>>>(freqs);

    k_gemm<<<dim3(8, 128), 256, GSMEM>>>(1, out);
}

// round 6
// speedup vs baseline: 3.2394x; 2.0846x over previous
#include <cuda_runtime.h>
#include <cuda_fp16.h>
#include <cstdint>

#define BB 2
#define TT 8192
#define DD 1024
#define MM (BB*TT)
#define PCH 128
#define TCH (TT/PCH)

// ----------------------------- device scratch ------------------------------
__device__ __align__(128) __half g_Xh[(size_t)MM*DD];
__device__ __align__(128) __half g_Wvh[DD*DD];
__device__ __align__(128) __half g_Woh[DD*DD];
__device__ __align__(128) __half g_V[(size_t)MM*DD];
__device__ __align__(128) float2 g_part[BB*PCH*DD];
__device__ __align__(128) __half g_Rh[(size_t)MM*DD];

// ------------------------------ PTX helpers --------------------------------
__device__ __forceinline__ uint32_t smem_to_u32(const void* p) {
    uint32_t a;
    asm("{ .reg .u64 t; cvta.to.shared.u64 t, %1; cvt.u32.u64 %0, t; }" : "=r"(a) : "l"(p));
    return a;
}
#define SWZ(o) ((uint32_t)(o) ^ ((((uint32_t)(o)) >> 3) & 0x70))

#define CP_ASYNC16(dst, src) \
    asm volatile("cp.async.cg.shared.global [%0], [%1], 16;" :: "r"(dst), "l"(src))
#define CP_COMMIT() asm volatile("cp.async.commit_group;" ::: "memory")
#define CP_WAIT1() asm volatile("cp.async.wait_group 1;" ::: "memory")
#define CP_WAIT0() asm volatile("cp.async.wait_group 0;" ::: "memory")

#define LDMX4(r0, r1, r2, r3, addr) \
    asm volatile("ldmatrix.sync.aligned.m8n8.x4.shared.b16 {%0,%1,%2,%3}, [%4];" \
        : "=r"(r0), "=r"(r1), "=r"(r2), "=r"(r3) : "r"(addr))

#define MMA16816(d, a, b) \
    asm volatile("mma.sync.aligned.m16n8k16.row.col.f32.f16.f16.f32 " \
        "{%0,%1,%2,%3}, {%4,%5,%6,%7}, {%8,%9}, {%0,%1,%2,%3};" \
        : "+f"((d)[0]), "+f"((d)[1]), "+f"((d)[2]), "+f"((d)[3]) \
        : "r"((a)[0]), "r"((a)[1]), "r"((a)[2]), "r"((a)[3]), \
          "r"((b)[0]), "r"((b)[1]))

// ------------------------------- split -------------------------------------
// fp32 -> fp16 (round-to-nearest)
__global__ void k_split(const float* __restrict__ in, int which) {
    size_t n; __half* hi;
    if (which == 0)      { n = (size_t)MM * DD; hi = g_Xh;  }
    else if (which == 1) { n = (size_t)DD * DD; hi = g_Wvh; }
    else                 { n = (size_t)DD * DD; hi = g_Woh; }
    size_t n4 = n >> 2;
    const float4* in4 = (const float4*)in;
    __half2* h2 = (__half2*)hi;
    for (size_t i = (size_t)blockIdx.x * blockDim.x + threadIdx.x; i < n4;
         i += (size_t)gridDim.x * blockDim.x) {
        float4 v = in4[i];
        __half2 a, b;
        a.x = __float2half(v.x); a.y = __float2half(v.y);
        b.x = __float2half(v.z); b.y = __float2half(v.w);
        h2[2*i] = a; h2[2*i+1] = b;
    }
}

// -------------------------------- GEMM -------------------------------------
// C[m,n] = sum_k A[m,k]*B[n,k], plain fp16 x fp16 -> fp32 accumulate.
// which==0: A=g_Xh, B=g_Wvh, C=g_V (fp16).  which==1: A=g_Rh, B=g_Woh, C=out (fp32).
#define TILEB 16384          // 128 rows x 128B
#define B_BASE 32768
#define GSMEM 65536
#define NCHUNK 16

__global__ void __launch_bounds__(256, 2)
k_gemm(int which, float* __restrict__ outC) {
    extern __shared__ __align__(1024) char smem[];
    const __half *Ah, *Bh;
    if (which == 0) { Ah = g_Xh; Bh = g_Wvh; }
    else            { Ah = g_Rh; Bh = g_Woh; }

    const uint32_t sb = smem_to_u32(smem);
    const int tid = threadIdx.x, wid = tid >> 5, lid = tid & 31;
    const int warp_m = wid & 3, warp_n = wid >> 2;
    const int tn = blockIdx.x * 128, tm = blockIdx.y * 128;

    float acc[2][8][4];
    #pragma unroll
    for (int mi = 0; mi < 2; ++mi)
        #pragma unroll
        for (int ni = 0; ni < 8; ++ni)
            #pragma unroll
            for (int q = 0; q < 4; ++q) acc[mi][ni][q] = 0.f;

    auto load_chunk = [&](int c, int buf) {
        const int k0 = c << 6;
        const char* srcA = (const char*)(Ah + (size_t)tm * DD + k0);
        const char* srcB = (const char*)(Bh + (size_t)tn * DD + k0);
        const uint32_t dA = sb + buf * TILEB;
        const uint32_t dB = sb + B_BASE + buf * TILEB;
        #pragma unroll
        for (int i = 0; i < 4; ++i) {
            int j = tid + i * 256;
            int row = j >> 3, seg = j & 7;
            uint32_t off = SWZ((row << 7) | (seg << 4));
            size_t goff = (size_t)row * (DD * 2) + seg * 16;
            CP_ASYNC16(dA + off, srcA + goff);
            CP_ASYNC16(dB + off, srcB + goff);
        }
        CP_COMMIT();
    };

    load_chunk(0, 0);

    const int a_row = warp_m * 32 + (lid & 7) + ((lid >> 3) & 1) * 8;
    const int a_kof = ((lid >> 4) & 1) * 8;
    const int b_row = warp_n * 64 + (lid & 7) + ((lid >> 4) & 1) * 8;
    const int b_kof = ((lid >> 3) & 1) * 8;

    for (int c = 0; c < NCHUNK; ++c) {
        if (c + 1 < NCHUNK) { load_chunk(c + 1, (c + 1) & 1); CP_WAIT1(); }
        else                { CP_WAIT0(); }
        __syncthreads();

        const uint32_t aB = sb + (c & 1) * TILEB;
        const uint32_t bB = sb + B_BASE + (c & 1) * TILEB;
        #pragma unroll
        for (int kk = 0; kk < 4; ++kk) {
            uint32_t af[2][4], bf[8][2];
            #pragma unroll
            for (int mi = 0; mi < 2; ++mi) {
                uint32_t addr = aB + SWZ(((a_row + mi * 16) << 7) | ((a_kof + kk * 16) << 1));
                LDMX4(af[mi][0], af[mi][1], af[mi][2], af[mi][3], addr);
            }
            #pragma unroll
            for (int ni = 0; ni < 4; ++ni) {
                uint32_t r0, r1, r2, r3;
                uint32_t addr = bB + SWZ(((b_row + ni * 16) << 7) | ((b_kof + kk * 16) << 1));
                LDMX4(r0, r1, r2, r3, addr);
                bf[2*ni][0] = r0; bf[2*ni][1] = r1;
                bf[2*ni+1][0] = r2; bf[2*ni+1][1] = r3;
            }
            #pragma unroll
            for (int mi = 0; mi < 2; ++mi)
                #pragma unroll
                for (int ni = 0; ni < 8; ++ni)
                    MMA16816(acc[mi][ni], af[mi], bf[ni]);
        }
        __syncthreads();
    }

    if (which == 0) {
        // fp16 output (V): acc pairs are n-contiguous -> __half2 stores
        #pragma unroll
        for (int mi = 0; mi < 2; ++mi) {
            int m = tm + warp_m * 32 + mi * 16 + (lid >> 2);
            int n0 = tn + warp_n * 64 + (lid & 3) * 2;
            __half* r0p = g_V + (size_t)m * DD + n0;
            __half* r1p = g_V + (size_t)(m + 8) * DD + n0;
            #pragma unroll
            for (int ni = 0; ni < 8; ++ni) {
                __half2 v0, v1;
                v0.x = __float2half(acc[mi][ni][0]); v0.y = __float2half(acc[mi][ni][1]);
                v1.x = __float2half(acc[mi][ni][2]); v1.y = __float2half(acc[mi][ni][3]);
                *(__half2*)(r0p + ni * 8) = v0;
                *(__half2*)(r1p + ni * 8) = v1;
            }
        }
    } else {
        #pragma unroll
        for (int mi = 0; mi < 2; ++mi) {
            int m = tm + warp_m * 32 + mi * 16 + (lid >> 2);
            int n0 = tn + warp_n * 64 + (lid & 3) * 2;
            float* r0p = outC + (size_t)m * DD + n0;
            float* r1p = outC + (size_t)(m + 8) * DD + n0;
            #pragma unroll
            for (int ni = 0; ni < 8; ++ni) {
                *(float2*)(r0p + ni * 8) = make_float2(acc[mi][ni][0], acc[mi][ni][1]);
                *(float2*)(r1p + ni * 8) = make_float2(acc[mi][ni][2], acc[mi][ni][3]);
            }
        }
    }
}

// ------------------------------- scan --------------------------------------
// ph = fl32(t*f) (exact reproduction of reference rounding), then 3-term fp32
// Cody-Waite reduction (constants compile-time; q<=8192 is 13-bit, H has 6-bit
// mantissa -> q*H exact). MUFU sin/cos on |r|<=pi.
__device__ __forceinline__ void rot_sincos(float ph, float* s, float* c) {
    constexpr double TP = 6.283185307179586;
    constexpr float H = 6.28125f;
    constexpr float Mv = (float)(TP - (double)H);
    constexpr float L  = (float)(TP - (double)H - (double)Mv);
    float q = rintf(ph * 0.15915494309189535f);
    float r = fmaf(q, -H, ph);
    r = fmaf(q, -Mv, r);
    r = fmaf(q, -L, r);
    *s = __sinf(r); *c = __cosf(r);
}

__global__ void k_pass1(const float* __restrict__ freqs) {
    const int b = blockIdx.y, ch = blockIdx.x, tid = threadIdx.x;
    float f[4]; float2 acc[4];
    #pragma unroll
    for (int j = 0; j < 4; ++j) { f[j] = freqs[tid + j*256]; acc[j] = make_float2(0.f, 0.f); }
    const __half* vp = g_V + ((size_t)b * TT + (size_t)ch * TCH) * DD + tid;
    for (int tl = 0; tl < TCH; ++tl) {
        float t = (float)(ch * TCH + tl);
        #pragma unroll
        for (int j = 0; j < 4; ++j) {
            float s, c; rot_sincos(t * f[j], &s, &c);
            float v = __half2float(vp[j*256]);
            acc[j].x += v * c; acc[j].y += v * s;
        }
        vp += DD;
    }
    #pragma unroll
    for (int j = 0; j < 4; ++j)
        g_part[((size_t)b * PCH + ch) * DD + tid + j*256] = acc[j];
}

__global__ void k_pass2() {
    int id = blockIdx.x * blockDim.x + threadIdx.x;   // 0..2047
    int b = id >> 10, d = id & 1023;
    float2 run = make_float2(0.f, 0.f);
    size_t base = (size_t)b * PCH * DD + d;
    for (int ch = 0; ch < PCH; ch += 4) {
        float2 v0 = g_part[base + (size_t)(ch+0)*DD];
        float2 v1 = g_part[base + (size_t)(ch+1)*DD];
        float2 v2 = g_part[base + (size_t)(ch+2)*DD];
        float2 v3 = g_part[base + (size_t)(ch+3)*DD];
        g_part[base + (size_t)(ch+0)*DD] = run; run.x += v0.x; run.y += v0.y;
        g_part[base + (size_t)(ch+1)*DD] = run; run.x += v1.x; run.y += v1.y;
        g_part[base + (size_t)(ch+2)*DD] = run; run.x += v2.x; run.y += v2.y;
        g_part[base + (size_t)(ch+3)*DD] = run; run.x += v3.x; run.y += v3.y;
    }
}

__global__ void k_pass3(const float* __restrict__ freqs) {
    const int b = blockIdx.y, ch = blockIdx.x, tid = threadIdx.x;
    float f[4]; float2 acc[4];
    #pragma unroll
    for (int j = 0; j < 4; ++j) {
        f[j] = freqs[tid + j*256];
        acc[j] = g_part[((size_t)b * PCH + ch) * DD + tid + j*256];
    }
    size_t base = ((size_t)b * TT + (size_t)ch * TCH) * DD + tid;
    const __half* vp = g_V + base;
    __half* rh = g_Rh + base;
    for (int tl = 0; tl < TCH; ++tl) {
        float t = (float)(ch * TCH + tl);
        #pragma unroll
        for (int j = 0; j < 4; ++j) {
            float s, c; rot_sincos(t * f[j], &s, &c);
            float v = __half2float(vp[j*256]);
            acc[j].x += v * c; acc[j].y += v * s;
            float ret = acc[j].x * c + acc[j].y * s;
            rh[j*256] = __float2half(ret);
        }
        vp += DD; rh += DD;
    }
}

// ------------------------------- launch ------------------------------------
extern "C" void kernel_launch(void* const* d_in, const int* in_sizes, int n_in,
                              void* d_out, int out_size) {
    const float* x     = (const float*)d_in[0];
    const float* Wv    = (const float*)d_in[2];
    const float* Wo    = (const float*)d_in[3];
    const float* freqs = (const float*)d_in[4];
    float* out = (float*)d_out;

    static int smem_set = 0;
    if (!smem_set) {
        cudaFuncSetAttribute(k_gemm, cudaFuncAttributeMaxDynamicSharedMemorySize, GSMEM);
        smem_set = 1;
    }

    k_split<<<2048, 256>>>(x, 0);
    k_split<<<256, 256>>>(Wv, 1);
    k_split<<<256, 256>>>(Wo, 2);

    k_gemm<<<dim3(8, 128), 256, GSMEM>>>(0, nullptr);

    k_pass1<<<dim3(PCH, BB), 256>>>(freqs);
    k_pass2<<<64, 32>>>();
    k_pass3<<<dim3(PCH, BB), 256>>>(freqs);

    k_gemm<<<dim3(8, 128), 256, GSMEM>>>(1, out);
}